// round 2
// baseline (speedup 1.0000x reference)
#include <cuda_runtime.h>
#include <math.h>

// Problem constants
#define N_ROWS 16384
#define F_FEAT 39
#define V_SZ   100000
#define E_DIM  16
#define HIDDEN 400
#define K1     (F_FEAT*E_DIM)   // 624
#define BN_EPS 1e-5f
#define MBLK   (N_ROWS/64)      // 256 row-blocks in each GEMM grid

// Scratch (static device globals — allocation-free as required)
__device__ __align__(16) float g_H0[(size_t)N_ROWS * K1];      // normalized xv, (N, 624)
__device__ __align__(16) float g_HA[(size_t)N_ROWS * HIDDEN];  // GEMM outputs (pre-BN)
__device__ __align__(16) float g_HB[(size_t)N_ROWS * HIDDEN];  // BN+ReLU outputs
__device__ __align__(16) float g_parts[MBLK * HIDDEN];         // per-block column sums
__device__ __align__(16) float g_partq[MBLK * HIDDEN];         // per-block column sums of squares
__device__ __align__(16) float g_sa[HIDDEN];                   // BN folded scale
__device__ __align__(16) float g_sc[HIDDEN];                   // BN folded shift

// ---------------------------------------------------------------------------
// Kernel 1: embedding gather + FM first/second order + feature-axis normalize.
// block = (16 e-lanes, 16 rows), grid = N/16.
// Writes g_H0 and out[n] = sum(f1) + sum(f2) + bias.
// NOTE: Xi is int32 (JAX x64 disabled downgrades the int64 request).
// ---------------------------------------------------------------------------
__global__ __launch_bounds__(256)
void gather_fm_kernel(const int* __restrict__ Xi,
                      const float* __restrict__ Xv,
                      const float* __restrict__ emb1,
                      const float* __restrict__ emb2,
                      const float* __restrict__ bias,
                      float* __restrict__ out)
{
    const int e = threadIdx.x;                 // 0..15 (embedding dim)
    const int r = threadIdx.y;                 // 0..15 (row in block)
    const int n = blockIdx.x * 16 + r;

    float arr[F_FEAT];
    float sumsq = 0.f;

    #pragma unroll
    for (int f = 0; f < F_FEAT; f++) {
        int idx = Xi[(size_t)n * F_FEAT + f];           // broadcast across e-lanes
        float xvf = Xv[(size_t)n * F_FEAT + f];
        float v = emb2[((size_t)f * V_SZ + (size_t)idx) * E_DIM + e] * xvf;
        arr[f] = v;
        sumsq = fmaf(v, v, sumsq);
    }

    float inv = 1.0f / fmaxf(sqrtf(sumsq), 1e-12f);

    float s = 0.f, ss = 0.f;
    #pragma unroll
    for (int f = 0; f < F_FEAT; f++) {
        float w = arr[f] * inv;
        s += w;
        ss = fmaf(w, w, ss);
        g_H0[(size_t)n * K1 + f * E_DIM + e] = w;
    }
    float val = 0.5f * (s * s - ss);           // f2 contribution for this e

    // f1 contribution: distribute features across e-lanes (f = e, e+16, e+32)
    for (int f = e; f < F_FEAT; f += 16) {
        int idx = Xi[(size_t)n * F_FEAT + f];
        val = fmaf(emb1[(size_t)f * V_SZ + (size_t)idx],
                   Xv[(size_t)n * F_FEAT + f], val);
    }

    // reduce across the 16 e-lanes (half-warp)
    #pragma unroll
    for (int off = 8; off > 0; off >>= 1)
        val += __shfl_down_sync(0xffffffffu, val, off, 16);

    if (e == 0) out[n] = val + bias[0];
}

// ---------------------------------------------------------------------------
// Kernel 2: fp32 tiled GEMM  C = A @ W^T + b  with fused per-column stats.
// A: (N_ROWS, KDIM) row-major, W: (HIDDEN, KDIM) row-major.
// Tile 64x64x16, 256 threads, 4x4 micro-tile. Deterministic block partials.
// SRC: 0=g_H0, 1=g_HA, 2=g_HB.  DST: 1=g_HA, 2=g_HB.
// ---------------------------------------------------------------------------
template<int KDIM, int SRC, int DST>
__global__ __launch_bounds__(256)
void gemm_kernel(const float* __restrict__ W, const float* __restrict__ bvec)
{
    const float* A = (SRC == 0) ? g_H0 : ((SRC == 1) ? g_HA : g_HB);
    float* C = (DST == 1) ? g_HA : g_HB;

    __shared__ float As[16][68];
    __shared__ float Bs[16][68];

    const int tid = threadIdx.x;
    const int m0 = blockIdx.x * 64;
    const int n0 = blockIdx.y * 64;
    const int tr = tid >> 4;          // 0..15 -> rows tr*4..tr*4+3
    const int tc = tid & 15;          // 0..15 -> cols tc*4..tc*4+3
    const int lm = tid >> 2;          // 0..63 load row
    const int lk = (tid & 3) << 2;    // 0,4,8,12 load k offset

    float acc[4][4];
    #pragma unroll
    for (int i = 0; i < 4; i++)
        #pragma unroll
        for (int j = 0; j < 4; j++) acc[i][j] = 0.f;

    const float* Aptr = A + (size_t)(m0 + lm) * KDIM + lk;
    const bool bvalid = (n0 + lm) < HIDDEN;
    const float* Wptr = W + (size_t)(n0 + lm) * KDIM + lk;

    for (int k0 = 0; k0 < KDIM; k0 += 16) {
        float4 a4 = *(const float4*)(Aptr + k0);
        float4 b4 = bvalid ? *(const float4*)(Wptr + k0)
                           : make_float4(0.f, 0.f, 0.f, 0.f);
        As[lk + 0][lm] = a4.x; As[lk + 1][lm] = a4.y;
        As[lk + 2][lm] = a4.z; As[lk + 3][lm] = a4.w;
        Bs[lk + 0][lm] = b4.x; Bs[lk + 1][lm] = b4.y;
        Bs[lk + 2][lm] = b4.z; Bs[lk + 3][lm] = b4.w;
        __syncthreads();

        #pragma unroll
        for (int kk = 0; kk < 16; kk++) {
            float4 av = *(const float4*)&As[kk][tr << 2];
            float4 bv = *(const float4*)&Bs[kk][tc << 2];
            acc[0][0] = fmaf(av.x, bv.x, acc[0][0]);
            acc[0][1] = fmaf(av.x, bv.y, acc[0][1]);
            acc[0][2] = fmaf(av.x, bv.z, acc[0][2]);
            acc[0][3] = fmaf(av.x, bv.w, acc[0][3]);
            acc[1][0] = fmaf(av.y, bv.x, acc[1][0]);
            acc[1][1] = fmaf(av.y, bv.y, acc[1][1]);
            acc[1][2] = fmaf(av.y, bv.z, acc[1][2]);
            acc[1][3] = fmaf(av.y, bv.w, acc[1][3]);
            acc[2][0] = fmaf(av.z, bv.x, acc[2][0]);
            acc[2][1] = fmaf(av.z, bv.y, acc[2][1]);
            acc[2][2] = fmaf(av.z, bv.z, acc[2][2]);
            acc[2][3] = fmaf(av.z, bv.w, acc[2][3]);
            acc[3][0] = fmaf(av.w, bv.x, acc[3][0]);
            acc[3][1] = fmaf(av.w, bv.y, acc[3][1]);
            acc[3][2] = fmaf(av.w, bv.z, acc[3][2]);
            acc[3][3] = fmaf(av.w, bv.w, acc[3][3]);
        }
        __syncthreads();
    }

    // Epilogue: add bias, store C, accumulate per-column partial sum/sumsq.
    float ps[4] = {0.f, 0.f, 0.f, 0.f};
    float pq[4] = {0.f, 0.f, 0.f, 0.f};
    #pragma unroll
    for (int j = 0; j < 4; j++) {
        int nn = n0 + (tc << 2) + j;
        if (nn < HIDDEN) {
            float bb = bvec[nn];
            #pragma unroll
            for (int i = 0; i < 4; i++) {
                float v = acc[i][j] + bb;
                C[(size_t)(m0 + (tr << 2) + i) * HIDDEN + nn] = v;
                ps[j] += v;
                pq[j] = fmaf(v, v, pq[j]);
            }
        }
    }

    // Deterministic intra-block column reduction (reuse As/Bs as scratch).
    #pragma unroll
    for (int j = 0; j < 4; j++) {
        As[tr][(tc << 2) + j] = ps[j];
        Bs[tr][(tc << 2) + j] = pq[j];
    }
    __syncthreads();
    if (tid < 64) {
        int nn = n0 + tid;
        if (nn < HIDDEN) {
            float s = 0.f, q = 0.f;
            #pragma unroll
            for (int rr = 0; rr < 16; rr++) { s += As[rr][tid]; q += Bs[rr][tid]; }
            g_parts[blockIdx.x * HIDDEN + nn] = s;
            g_partq[blockIdx.x * HIDDEN + nn] = q;
        }
    }
}

// ---------------------------------------------------------------------------
// Kernel 3: finalize BN stats -> folded scale/shift. grid = 400, block = 256
// (one thread per row-block partial; MBLK == 256 exactly).
// ---------------------------------------------------------------------------
__global__ __launch_bounds__(256)
void finalize_kernel(const float* __restrict__ g, const float* __restrict__ bt)
{
    const int col = blockIdx.x;
    const int tid = threadIdx.x;
    __shared__ float ss[256];
    __shared__ float sq[256];
    ss[tid] = g_parts[tid * HIDDEN + col];
    sq[tid] = g_partq[tid * HIDDEN + col];
    __syncthreads();
    #pragma unroll
    for (int st = 128; st > 0; st >>= 1) {
        if (tid < st) { ss[tid] += ss[tid + st]; sq[tid] += sq[tid + st]; }
        __syncthreads();
    }
    if (tid == 0) {
        float mu  = ss[0] * (1.0f / N_ROWS);
        float var = sq[0] * (1.0f / N_ROWS) - mu * mu;
        float a = g[col] * rsqrtf(var + BN_EPS);
        g_sa[col] = a;
        g_sc[col] = fmaf(-a, mu, bt[col]);
    }
}

// ---------------------------------------------------------------------------
// Kernel 4: BN + ReLU elementwise, g_HA -> g_HB, float4 vectorized.
// ---------------------------------------------------------------------------
__global__ __launch_bounds__(256)
void bn_relu_kernel()
{
    const int total = N_ROWS * HIDDEN / 4;
    int i = blockIdx.x * blockDim.x + threadIdx.x;
    if (i < total) {
        float4 v = ((const float4*)g_HA)[i];
        int c0 = (i % (HIDDEN / 4)) * 4;
        v.x = fmaxf(fmaf(g_sa[c0 + 0], v.x, g_sc[c0 + 0]), 0.f);
        v.y = fmaxf(fmaf(g_sa[c0 + 1], v.y, g_sc[c0 + 1]), 0.f);
        v.z = fmaxf(fmaf(g_sa[c0 + 2], v.z, g_sc[c0 + 2]), 0.f);
        v.w = fmaxf(fmaf(g_sa[c0 + 3], v.w, g_sc[c0 + 3]), 0.f);
        ((float4*)g_HB)[i] = v;
    }
}

// ---------------------------------------------------------------------------
// Kernel 5: final BN + ReLU fused with row-sum, adds into out[n].
// One warp per row.
// ---------------------------------------------------------------------------
__global__ __launch_bounds__(256)
void bn_relu_rowsum_kernel(float* __restrict__ out)
{
    const int warp = threadIdx.x >> 5;
    const int lane = threadIdx.x & 31;
    const int n = (blockIdx.x << 3) + warp;
    const float* row = g_HA + (size_t)n * HIDDEN;
    float s = 0.f;
    for (int c = lane; c < HIDDEN; c += 32)
        s += fmaxf(fmaf(g_sa[c], row[c], g_sc[c]), 0.f);
    #pragma unroll
    for (int off = 16; off > 0; off >>= 1)
        s += __shfl_xor_sync(0xffffffffu, s, off);
    if (lane == 0) out[n] += s;
}

// ---------------------------------------------------------------------------
extern "C" void kernel_launch(void* const* d_in, const int* in_sizes, int n_in,
                              void* d_out, int out_size)
{
    const int* Xi        = (const int*)d_in[0];
    const float* Xv      = (const float*)d_in[1];
    const float* emb1    = (const float*)d_in[2];
    const float* emb2    = (const float*)d_in[3];
    const float* W1      = (const float*)d_in[4];
    const float* b1      = (const float*)d_in[5];
    const float* g1      = (const float*)d_in[6];
    const float* bt1     = (const float*)d_in[7];
    const float* W2      = (const float*)d_in[8];
    const float* b2      = (const float*)d_in[9];
    const float* g2      = (const float*)d_in[10];
    const float* bt2     = (const float*)d_in[11];
    const float* W3      = (const float*)d_in[12];
    const float* b3      = (const float*)d_in[13];
    const float* g3      = (const float*)d_in[14];
    const float* bt3     = (const float*)d_in[15];
    const float* bias    = (const float*)d_in[16];
    float* out = (float*)d_out;

    // 1. Gather + FM terms + normalize; writes H0 and out = f1+f2+bias
    gather_fm_kernel<<<N_ROWS / 16, dim3(16, 16)>>>(Xi, Xv, emb1, emb2, bias, out);

    dim3 ggrid(MBLK, (HIDDEN + 63) / 64);   // (256, 7)
    const int bn_total = N_ROWS * HIDDEN / 4;
    const int bn_grid = (bn_total + 255) / 256;

    // Layer 1: H0(624) -> HA
    gemm_kernel<K1, 0, 1><<<ggrid, 256>>>(W1, b1);
    finalize_kernel<<<HIDDEN, 256>>>(g1, bt1);
    bn_relu_kernel<<<bn_grid, 256>>>();     // HA -> HB

    // Layer 2: HB(400) -> HA
    gemm_kernel<HIDDEN, 2, 1><<<ggrid, 256>>>(W2, b2);
    finalize_kernel<<<HIDDEN, 256>>>(g2, bt2);
    bn_relu_kernel<<<bn_grid, 256>>>();     // HA -> HB

    // Layer 3: HB(400) -> HA
    gemm_kernel<HIDDEN, 2, 1><<<ggrid, 256>>>(W3, b3);
    finalize_kernel<<<HIDDEN, 256>>>(g3, bt3);

    // Final BN+ReLU fused with row-sum into out
    bn_relu_rowsum_kernel<<<N_ROWS / 8, 256>>>(out);
}

// round 3
// speedup vs baseline: 1.4365x; 1.4365x over previous
#include <cuda_runtime.h>
#include <math.h>

// Problem constants
#define N_ROWS 16384
#define F_FEAT 39
#define V_SZ   100000
#define E_DIM  16
#define HIDDEN 400
#define K1     (F_FEAT*E_DIM)   // 624
#define BN_EPS 1e-5f
#define MBLK   (N_ROWS/128)     // 128 row-blocks in the TC GEMM grid

// Scratch (static device globals — allocation-free as required)
__device__ __align__(16) float g_H0[(size_t)N_ROWS * K1];      // normalized xv, (N, 624)
__device__ __align__(16) float g_HA[(size_t)N_ROWS * HIDDEN];  // layer 1/3 outputs (pre-BN)
__device__ __align__(16) float g_HB[(size_t)N_ROWS * HIDDEN];  // layer 2 output (pre-BN)
__device__ __align__(16) float g_parts[MBLK * HIDDEN];         // per-block column sums
__device__ __align__(16) float g_partq[MBLK * HIDDEN];         // per-block column sumsq
__device__ __align__(16) float g_sa[HIDDEN];                   // BN folded scale
__device__ __align__(16) float g_sc[HIDDEN];                   // BN folded shift

__device__ __forceinline__ unsigned f2tf(float f) {
    unsigned u;
    asm("cvt.rna.tf32.f32 %0, %1;" : "=r"(u) : "f"(f));
    return u;
}

// ---------------------------------------------------------------------------
// Kernel 1: embedding gather + FM first/second order + feature-axis normalize.
// block = (16 e-lanes, 16 rows), grid = N/16.  Xi is int32.
// ---------------------------------------------------------------------------
__global__ __launch_bounds__(256)
void gather_fm_kernel(const int* __restrict__ Xi,
                      const float* __restrict__ Xv,
                      const float* __restrict__ emb1,
                      const float* __restrict__ emb2,
                      const float* __restrict__ bias,
                      float* __restrict__ out)
{
    const int e = threadIdx.x;
    const int r = threadIdx.y;
    const int n = blockIdx.x * 16 + r;

    float arr[F_FEAT];
    float sumsq = 0.f;

    #pragma unroll
    for (int f = 0; f < F_FEAT; f++) {
        int idx = Xi[(size_t)n * F_FEAT + f];
        float xvf = Xv[(size_t)n * F_FEAT + f];
        float v = emb2[((size_t)f * V_SZ + (size_t)idx) * E_DIM + e] * xvf;
        arr[f] = v;
        sumsq = fmaf(v, v, sumsq);
    }

    float inv = 1.0f / fmaxf(sqrtf(sumsq), 1e-12f);

    float s = 0.f, ss = 0.f;
    #pragma unroll
    for (int f = 0; f < F_FEAT; f++) {
        float w = arr[f] * inv;
        s += w;
        ss = fmaf(w, w, ss);
        g_H0[(size_t)n * K1 + f * E_DIM + e] = w;
    }
    float val = 0.5f * (s * s - ss);

    for (int f = e; f < F_FEAT; f += 16) {
        int idx = Xi[(size_t)n * F_FEAT + f];
        val = fmaf(emb1[(size_t)f * V_SZ + (size_t)idx],
                   Xv[(size_t)n * F_FEAT + f], val);
    }

    #pragma unroll
    for (int off = 8; off > 0; off >>= 1)
        val += __shfl_down_sync(0xffffffffu, val, off, 16);

    if (e == 0) out[n] = val + bias[0];
}

// ---------------------------------------------------------------------------
// Kernel 2: TF32 tensor-core GEMM  C = act(A) @ W^T + b  with fused BN-apply
// on the A operand (when BN=true: A' = relu(sa[k]*A + sc[k])) and fused
// per-column stats for the NEXT BN.
// Block tile 128x64, 256 threads (8 warps: 4 m-warps x 2 n-warps),
// warp tile 32x32 = 2x4 mma(m16n8k8) tiles. K-chunk 16, reg double buffer.
// SRC: 0=g_H0, 1=g_HA, 2=g_HB.  DST: 1=g_HA, 2=g_HB.
// ---------------------------------------------------------------------------
template<int KDIM, bool BN, int SRC, int DST>
__global__ __launch_bounds__(256)
void gemm_tc_kernel(const float* __restrict__ W, const float* __restrict__ bvec)
{
    const float* A = (SRC == 0) ? g_H0 : ((SRC == 1) ? g_HA : g_HB);
    float* C = (DST == 1) ? g_HA : g_HB;

    __shared__ float As[16][132];   // [k][m], pad -> conflict-free frag loads
    __shared__ float Bs[16][68];    // [k][n]
    __shared__ float redS[4][64];
    __shared__ float redQ[4][64];

    const int tid   = threadIdx.x;
    const int lane  = tid & 31;
    const int warp  = tid >> 5;
    const int mwarp = warp >> 1;    // 0..3
    const int nwarp = warp & 1;     // 0..1
    const int m0 = blockIdx.x * 128;
    const int n0 = blockIdx.y * 64;

    // staging mapping
    const int ar  = tid & 127;            // A row 0..127
    const int ak  = (tid >> 7) << 3;      // 0 or 8
    const int brn = tid & 63;             // B row (n) 0..63
    const int bk4 = (tid >> 6) << 2;      // 0,4,8,12

    const float* Ap = A + (size_t)(m0 + ar) * KDIM + ak;
    const bool  bok = (n0 + brn) < HIDDEN;
    const float* Bp = W + (size_t)(n0 + brn) * KDIM + bk4;

    float c[2][4][4];
    #pragma unroll
    for (int mt = 0; mt < 2; mt++)
        #pragma unroll
        for (int nt = 0; nt < 4; nt++)
            #pragma unroll
            for (int i = 0; i < 4; i++) c[mt][nt][i] = 0.f;

    const int gq = lane >> 2;   // 0..7
    const int gr = lane & 3;    // 0..3

    float4 pa0, pa1, pb;

    // prefetch chunk 0
    {
        pa0 = *(const float4*)(Ap);
        pa1 = *(const float4*)(Ap + 4);
        pb  = bok ? *(const float4*)(Bp) : make_float4(0.f, 0.f, 0.f, 0.f);
        if (BN) {
            float4 s0 = *(const float4*)&g_sa[ak];
            float4 h0 = *(const float4*)&g_sc[ak];
            float4 s1 = *(const float4*)&g_sa[ak + 4];
            float4 h1 = *(const float4*)&g_sc[ak + 4];
            pa0.x = fmaxf(fmaf(s0.x, pa0.x, h0.x), 0.f);
            pa0.y = fmaxf(fmaf(s0.y, pa0.y, h0.y), 0.f);
            pa0.z = fmaxf(fmaf(s0.z, pa0.z, h0.z), 0.f);
            pa0.w = fmaxf(fmaf(s0.w, pa0.w, h0.w), 0.f);
            pa1.x = fmaxf(fmaf(s1.x, pa1.x, h1.x), 0.f);
            pa1.y = fmaxf(fmaf(s1.y, pa1.y, h1.y), 0.f);
            pa1.z = fmaxf(fmaf(s1.z, pa1.z, h1.z), 0.f);
            pa1.w = fmaxf(fmaf(s1.w, pa1.w, h1.w), 0.f);
        }
    }

    for (int k0 = 0; k0 < KDIM; k0 += 16) {
        // stage current chunk (converted to tf32)
        As[ak + 0][ar] = __uint_as_float(f2tf(pa0.x));
        As[ak + 1][ar] = __uint_as_float(f2tf(pa0.y));
        As[ak + 2][ar] = __uint_as_float(f2tf(pa0.z));
        As[ak + 3][ar] = __uint_as_float(f2tf(pa0.w));
        As[ak + 4][ar] = __uint_as_float(f2tf(pa1.x));
        As[ak + 5][ar] = __uint_as_float(f2tf(pa1.y));
        As[ak + 6][ar] = __uint_as_float(f2tf(pa1.z));
        As[ak + 7][ar] = __uint_as_float(f2tf(pa1.w));
        Bs[bk4 + 0][brn] = __uint_as_float(f2tf(pb.x));
        Bs[bk4 + 1][brn] = __uint_as_float(f2tf(pb.y));
        Bs[bk4 + 2][brn] = __uint_as_float(f2tf(pb.z));
        Bs[bk4 + 3][brn] = __uint_as_float(f2tf(pb.w));
        __syncthreads();

        // prefetch next chunk (overlaps with mma compute)
        if (k0 + 16 < KDIM) {
            int kn = k0 + 16;
            pa0 = *(const float4*)(Ap + kn);
            pa1 = *(const float4*)(Ap + kn + 4);
            pb  = bok ? *(const float4*)(Bp + kn) : make_float4(0.f, 0.f, 0.f, 0.f);
            if (BN) {
                float4 s0 = *(const float4*)&g_sa[kn + ak];
                float4 h0 = *(const float4*)&g_sc[kn + ak];
                float4 s1 = *(const float4*)&g_sa[kn + ak + 4];
                float4 h1 = *(const float4*)&g_sc[kn + ak + 4];
                pa0.x = fmaxf(fmaf(s0.x, pa0.x, h0.x), 0.f);
                pa0.y = fmaxf(fmaf(s0.y, pa0.y, h0.y), 0.f);
                pa0.z = fmaxf(fmaf(s0.z, pa0.z, h0.z), 0.f);
                pa0.w = fmaxf(fmaf(s0.w, pa0.w, h0.w), 0.f);
                pa1.x = fmaxf(fmaf(s1.x, pa1.x, h1.x), 0.f);
                pa1.y = fmaxf(fmaf(s1.y, pa1.y, h1.y), 0.f);
                pa1.z = fmaxf(fmaf(s1.z, pa1.z, h1.z), 0.f);
                pa1.w = fmaxf(fmaf(s1.w, pa1.w, h1.w), 0.f);
            }
        }

        // compute: 2 k-steps of 8
        #pragma unroll
        for (int ks = 0; ks < 16; ks += 8) {
            unsigned a[2][4], b[4][2];
            #pragma unroll
            for (int mt = 0; mt < 2; mt++) {
                int m = mwarp * 32 + mt * 16 + gq;
                a[mt][0] = __float_as_uint(As[ks + gr    ][m]);
                a[mt][1] = __float_as_uint(As[ks + gr    ][m + 8]);
                a[mt][2] = __float_as_uint(As[ks + gr + 4][m]);
                a[mt][3] = __float_as_uint(As[ks + gr + 4][m + 8]);
            }
            #pragma unroll
            for (int nt = 0; nt < 4; nt++) {
                int n = nwarp * 32 + nt * 8 + gq;
                b[nt][0] = __float_as_uint(Bs[ks + gr    ][n]);
                b[nt][1] = __float_as_uint(Bs[ks + gr + 4][n]);
            }
            #pragma unroll
            for (int mt = 0; mt < 2; mt++)
                #pragma unroll
                for (int nt = 0; nt < 4; nt++) {
                    asm volatile(
                        "mma.sync.aligned.m16n8k8.row.col.f32.tf32.tf32.f32 "
                        "{%0,%1,%2,%3}, {%4,%5,%6,%7}, {%8,%9}, {%0,%1,%2,%3};\n"
                        : "+f"(c[mt][nt][0]), "+f"(c[mt][nt][1]),
                          "+f"(c[mt][nt][2]), "+f"(c[mt][nt][3])
                        : "r"(a[mt][0]), "r"(a[mt][1]), "r"(a[mt][2]), "r"(a[mt][3]),
                          "r"(b[nt][0]), "r"(b[nt][1]));
                }
        }
        __syncthreads();
    }

    // ---------------- Epilogue: bias, store, per-column stats ----------------
    float sS[4][2], sQ[4][2];
    #pragma unroll
    for (int nt = 0; nt < 4; nt++) { sS[nt][0] = sS[nt][1] = 0.f; sQ[nt][0] = sQ[nt][1] = 0.f; }

    #pragma unroll
    for (int nt = 0; nt < 4; nt++) {
        int col = n0 + nwarp * 32 + nt * 8 + 2 * gr;
        bool cok = col < HIDDEN;   // col even, HIDDEN even -> col+1 also in range
        float bb0 = cok ? bvec[col]     : 0.f;
        float bb1 = cok ? bvec[col + 1] : 0.f;
        #pragma unroll
        for (int mt = 0; mt < 2; mt++) {
            int r0 = m0 + mwarp * 32 + mt * 16 + gq;
            float v00 = c[mt][nt][0] + bb0;
            float v01 = c[mt][nt][1] + bb1;
            float v10 = c[mt][nt][2] + bb0;
            float v11 = c[mt][nt][3] + bb1;
            if (cok) {
                *(float2*)&C[(size_t)r0 * HIDDEN + col]       = make_float2(v00, v01);
                *(float2*)&C[(size_t)(r0 + 8) * HIDDEN + col] = make_float2(v10, v11);
            }
            sS[nt][0] += v00 + v10;
            sS[nt][1] += v01 + v11;
            sQ[nt][0] = fmaf(v00, v00, fmaf(v10, v10, sQ[nt][0]));
            sQ[nt][1] = fmaf(v01, v01, fmaf(v11, v11, sQ[nt][1]));
        }
    }

    // reduce over the 8 row-groups (lane>>2) within the warp
    #pragma unroll
    for (int nt = 0; nt < 4; nt++)
        #pragma unroll
        for (int p = 0; p < 2; p++) {
            #pragma unroll
            for (int off = 4; off <= 16; off <<= 1) {
                sS[nt][p] += __shfl_xor_sync(0xffffffffu, sS[nt][p], off);
                sQ[nt][p] += __shfl_xor_sync(0xffffffffu, sQ[nt][p], off);
            }
        }
    if (gq == 0) {  // lanes 0..3
        #pragma unroll
        for (int nt = 0; nt < 4; nt++)
            #pragma unroll
            for (int p = 0; p < 2; p++) {
                int cl = nwarp * 32 + nt * 8 + 2 * gr + p;
                redS[mwarp][cl] = sS[nt][p];
                redQ[mwarp][cl] = sQ[nt][p];
            }
    }
    __syncthreads();
    if (tid < 64) {
        int col = n0 + tid;
        if (col < HIDDEN) {
            float s = redS[0][tid] + redS[1][tid] + redS[2][tid] + redS[3][tid];
            float q = redQ[0][tid] + redQ[1][tid] + redQ[2][tid] + redQ[3][tid];
            g_parts[blockIdx.x * HIDDEN + col] = s;
            g_partq[blockIdx.x * HIDDEN + col] = q;
        }
    }
}

// ---------------------------------------------------------------------------
// Kernel 3: finalize BN stats -> folded scale/shift. grid=400, block=128.
// ---------------------------------------------------------------------------
__global__ __launch_bounds__(128)
void finalize_kernel(const float* __restrict__ g, const float* __restrict__ bt)
{
    const int col = blockIdx.x;
    const int tid = threadIdx.x;
    __shared__ float ss[128];
    __shared__ float sq[128];
    ss[tid] = g_parts[tid * HIDDEN + col];
    sq[tid] = g_partq[tid * HIDDEN + col];
    __syncthreads();
    #pragma unroll
    for (int st = 64; st > 0; st >>= 1) {
        if (tid < st) { ss[tid] += ss[tid + st]; sq[tid] += sq[tid + st]; }
        __syncthreads();
    }
    if (tid == 0) {
        float mu  = ss[0] * (1.0f / N_ROWS);
        float var = sq[0] * (1.0f / N_ROWS) - mu * mu;
        float a = g[col] * rsqrtf(var + BN_EPS);
        g_sa[col] = a;
        g_sc[col] = fmaf(-a, mu, bt[col]);
    }
}

// ---------------------------------------------------------------------------
// Kernel 4: final BN + ReLU fused with row-sum, adds into out[n].
// One warp per row, reads g_HA (layer-3 pre-BN output).
// ---------------------------------------------------------------------------
__global__ __launch_bounds__(256)
void bn_relu_rowsum_kernel(float* __restrict__ out)
{
    const int warp = threadIdx.x >> 5;
    const int lane = threadIdx.x & 31;
    const int n = (blockIdx.x << 3) + warp;
    const float* row = g_HA + (size_t)n * HIDDEN;
    float s = 0.f;
    for (int c = lane; c < HIDDEN; c += 32)
        s += fmaxf(fmaf(g_sa[c], row[c], g_sc[c]), 0.f);
    #pragma unroll
    for (int off = 16; off > 0; off >>= 1)
        s += __shfl_xor_sync(0xffffffffu, s, off);
    if (lane == 0) out[n] += s;
}

// ---------------------------------------------------------------------------
extern "C" void kernel_launch(void* const* d_in, const int* in_sizes, int n_in,
                              void* d_out, int out_size)
{
    const int* Xi        = (const int*)d_in[0];
    const float* Xv      = (const float*)d_in[1];
    const float* emb1    = (const float*)d_in[2];
    const float* emb2    = (const float*)d_in[3];
    const float* W1      = (const float*)d_in[4];
    const float* b1      = (const float*)d_in[5];
    const float* g1      = (const float*)d_in[6];
    const float* bt1     = (const float*)d_in[7];
    const float* W2      = (const float*)d_in[8];
    const float* b2      = (const float*)d_in[9];
    const float* g2      = (const float*)d_in[10];
    const float* bt2     = (const float*)d_in[11];
    const float* W3      = (const float*)d_in[12];
    const float* b3      = (const float*)d_in[13];
    const float* g3      = (const float*)d_in[14];
    const float* bt3     = (const float*)d_in[15];
    const float* bias    = (const float*)d_in[16];
    float* out = (float*)d_out;

    gather_fm_kernel<<<N_ROWS / 16, dim3(16, 16)>>>(Xi, Xv, emb1, emb2, bias, out);

    dim3 ggrid(MBLK, (HIDDEN + 63) / 64);   // (128, 7)

    // Layer 1: H0(624) -> HA  (no BN on input)
    gemm_tc_kernel<K1, false, 0, 1><<<ggrid, 256>>>(W1, b1);
    finalize_kernel<<<HIDDEN, 128>>>(g1, bt1);

    // Layer 2: BN1(HA)(400) -> HB
    gemm_tc_kernel<HIDDEN, true, 1, 2><<<ggrid, 256>>>(W2, b2);
    finalize_kernel<<<HIDDEN, 128>>>(g2, bt2);

    // Layer 3: BN2(HB)(400) -> HA
    gemm_tc_kernel<HIDDEN, true, 2, 1><<<ggrid, 256>>>(W3, b3);
    finalize_kernel<<<HIDDEN, 128>>>(g3, bt3);

    // Final BN+ReLU fused with row-sum into out
    bn_relu_rowsum_kernel<<<N_ROWS / 8, 256>>>(out);
}

// round 6
// speedup vs baseline: 1.8287x; 1.2731x over previous
#include <cuda_runtime.h>
#include <cuda_bf16.h>
#include <math.h>

// Problem constants
#define N_ROWS 16384
#define F_FEAT 39
#define V_SZ   100000
#define E_DIM  16
#define HIDDEN 400
#define K1     (F_FEAT*E_DIM)   // 624
#define BN_EPS 1e-5f
#define MBLK   (N_ROWS/128)     // 128 row-blocks in the GEMM grid

// ---------------- scratch (allocation-free) ----------------
__device__ __align__(16) float g_H0[(size_t)N_ROWS * K1];
__device__ __align__(16) float g_HA[(size_t)N_ROWS * HIDDEN];
__device__ __align__(16) float g_HB[(size_t)N_ROWS * HIDDEN];
__device__ __align__(16) float g_parts[MBLK * HIDDEN];
__device__ __align__(16) float g_partq[MBLK * HIDDEN];
__device__ __align__(16) float g_sa[HIDDEN];
__device__ __align__(16) float g_sc[HIDDEN];

__device__ __forceinline__ unsigned smem_u32(const void* p) {
    unsigned a;
    asm("{ .reg .u64 t; cvta.to.shared.u64 t, %1; cvt.u32.u64 %0, t; }" : "=r"(a) : "l"(p));
    return a;
}

#define LDSM_X4(r0, r1, r2, r3, addr) \
    asm volatile("ldmatrix.sync.aligned.m8n8.x4.shared.b16 {%0,%1,%2,%3}, [%4];" \
                 : "=r"(r0), "=r"(r1), "=r"(r2), "=r"(r3) : "r"(addr))

#define MMA_BF16(cc, a, b0, b1) \
    asm volatile("mma.sync.aligned.m16n8k16.row.col.f32.bf16.bf16.f32 " \
                 "{%0,%1,%2,%3},{%4,%5,%6,%7},{%8,%9},{%0,%1,%2,%3};" \
                 : "+f"((cc)[0]), "+f"((cc)[1]), "+f"((cc)[2]), "+f"((cc)[3]) \
                 : "r"((a)[0]), "r"((a)[1]), "r"((a)[2]), "r"((a)[3]), \
                   "r"(b0), "r"(b1))

__device__ __forceinline__ unsigned pack2(__nv_bfloat16 a, __nv_bfloat16 b) {
    return ((unsigned)__bfloat16_as_ushort(b) << 16) | (unsigned)__bfloat16_as_ushort(a);
}
__device__ __forceinline__ void split4(float4 x, unsigned& h0, unsigned& h1,
                                       unsigned& l0, unsigned& l1) {
    __nv_bfloat16 a = __float2bfloat16(x.x), b = __float2bfloat16(x.y);
    __nv_bfloat16 c = __float2bfloat16(x.z), d = __float2bfloat16(x.w);
    h0 = pack2(a, b); h1 = pack2(c, d);
    l0 = pack2(__float2bfloat16(x.x - __bfloat162float(a)),
               __float2bfloat16(x.y - __bfloat162float(b)));
    l1 = pack2(__float2bfloat16(x.z - __bfloat162float(c)),
               __float2bfloat16(x.w - __bfloat162float(d)));
}
__device__ __forceinline__ float4 bn_relu4(float4 x, int k) {
    float4 s = *(const float4*)&g_sa[k];
    float4 c = *(const float4*)&g_sc[k];
    x.x = fmaxf(fmaf(s.x, x.x, c.x), 0.f);
    x.y = fmaxf(fmaf(s.y, x.y, c.y), 0.f);
    x.z = fmaxf(fmaf(s.z, x.z, c.z), 0.f);
    x.w = fmaxf(fmaf(s.w, x.w, c.w), 0.f);
    return x;
}

// ---------------------------------------------------------------------------
// Kernel 1: gather + FM terms + normalize (validated in R2/R3)
// ---------------------------------------------------------------------------
__global__ __launch_bounds__(256)
void gather_fm_kernel(const int* __restrict__ Xi, const float* __restrict__ Xv,
                      const float* __restrict__ emb1, const float* __restrict__ emb2,
                      const float* __restrict__ bias, float* __restrict__ out)
{
    const int e = threadIdx.x;
    const int r = threadIdx.y;
    const int n = blockIdx.x * 16 + r;

    float arr[F_FEAT];
    float sumsq = 0.f;
    #pragma unroll
    for (int f = 0; f < F_FEAT; f++) {
        int idx = Xi[(size_t)n * F_FEAT + f];
        float xvf = Xv[(size_t)n * F_FEAT + f];
        float v = emb2[((size_t)f * V_SZ + (size_t)idx) * E_DIM + e] * xvf;
        arr[f] = v;
        sumsq = fmaf(v, v, sumsq);
    }
    float inv = 1.0f / fmaxf(sqrtf(sumsq), 1e-12f);
    float s = 0.f, ss = 0.f;
    #pragma unroll
    for (int f = 0; f < F_FEAT; f++) {
        float w = arr[f] * inv;
        s += w; ss = fmaf(w, w, ss);
        g_H0[(size_t)n * K1 + f * E_DIM + e] = w;
    }
    float val = 0.5f * (s * s - ss);
    for (int f = e; f < F_FEAT; f += 16) {
        int idx = Xi[(size_t)n * F_FEAT + f];
        val = fmaf(emb1[(size_t)f * V_SZ + (size_t)idx], Xv[(size_t)n * F_FEAT + f], val);
    }
    #pragma unroll
    for (int off = 8; off > 0; off >>= 1)
        val += __shfl_down_sync(0xffffffffu, val, off, 16);
    if (e == 0) out[n] = val + bias[0];
}

// ---------------------------------------------------------------------------
// Kernel 2: bf16-split ldmatrix GEMM  C = act(A) @ W^T + b.
// CTA 128x64, 256 threads = 8 warps (4m x 2n), warp tile 32x32.
// Single-buffered static smem, K-chunk 32.
// 3-term split: hi*hi + lo*hi + hi*lo (fp32 accum).
// SRC: 0=g_H0, 1=g_HA, 2=g_HB.  DST: 1=g_HA, 2=g_HB.
// ---------------------------------------------------------------------------
template<int KDIM, bool BN, int SRC, int DST>
__global__ __launch_bounds__(256)
void gemm_bf16s(const float* __restrict__ W, const float* __restrict__ bvec)
{
    // rows padded to 40 bf16 (80 bytes): 16B-aligned rows, LDSM conflict-free
    __shared__ __align__(16) unsigned short sAhi[128 * 40];
    __shared__ __align__(16) unsigned short sAlo[128 * 40];
    __shared__ __align__(16) unsigned short sBhi[64 * 40];
    __shared__ __align__(16) unsigned short sBlo[64 * 40];
    __shared__ float redS[256];
    __shared__ float redQ[256];

    const float* A = (SRC == 0) ? g_H0 : ((SRC == 1) ? g_HA : g_HB);
    float* C = (DST == 1) ? g_HA : g_HB;

    const int tid   = threadIdx.x;
    const int lane  = tid & 31;
    const int warp  = tid >> 5;
    const int mwarp = warp >> 1;    // 0..3
    const int nwarp = warp & 1;     // 0..1
    const int m0 = blockIdx.x * 128;
    const int n0 = blockIdx.y * 64;

    // staging mapping
    const int arow = tid >> 1;            // 0..127
    const int acb  = (tid & 1) * 16;      // 0 or 16
    const int brow = tid >> 2;            // 0..63
    const int bcb  = (tid & 3) * 8;       // 0,8,16,24
    const float* ap = A + (size_t)(m0 + arow) * KDIM;
    const bool  bok = (n0 + brow) < HIDDEN;
    const float* bp = W + (size_t)(n0 + brow) * KDIM;

    const unsigned uAhi = smem_u32(sAhi);
    const unsigned uAlo = smem_u32(sAlo);
    const unsigned uBhi = smem_u32(sBhi);
    const unsigned uBlo = smem_u32(sBlo);

    // ldmatrix per-thread base offsets (bytes), row stride 80B
    const unsigned aoff = (mwarp * 32 + (lane & 15)) * 80 + (lane >> 4) * 16;
    const unsigned boff = (nwarp * 32 + ((lane >> 4) << 3) + (lane & 7)) * 80
                        + ((lane >> 3) & 1) * 16;

    float c[2][4][4];
    #pragma unroll
    for (int mt = 0; mt < 2; mt++)
        #pragma unroll
        for (int nt = 0; nt < 4; nt++)
            #pragma unroll
            for (int i = 0; i < 4; i++) c[mt][nt][i] = 0.f;

    const int nch = (KDIM + 31) / 32;

    for (int ch = 0; ch < nch; ch++) {
        const int kb = ch * 32;
        __syncthreads();   // previous chunk's compute done

        // ---- stage A (thread: row arow, cols acb..acb+15) ----
        #pragma unroll
        for (int j = 0; j < 4; j++) {
            int gk = kb + acb + 4 * j;
            float4 x = make_float4(0.f, 0.f, 0.f, 0.f);
            if (gk < KDIM) {
                x = *(const float4*)(ap + gk);
                if (BN) x = bn_relu4(x, gk);
            }
            unsigned h0, h1, l0, l1;
            split4(x, h0, h1, l0, l1);
            int o = arow * 40 + acb + 4 * j;
            *(uint2*)&sAhi[o] = make_uint2(h0, h1);
            *(uint2*)&sAlo[o] = make_uint2(l0, l1);
        }
        // ---- stage B (thread: row brow, cols bcb..bcb+7) ----
        #pragma unroll
        for (int j = 0; j < 2; j++) {
            int gk = kb + bcb + 4 * j;
            float4 x = make_float4(0.f, 0.f, 0.f, 0.f);
            if (bok && gk < KDIM) x = *(const float4*)(bp + gk);
            unsigned h0, h1, l0, l1;
            split4(x, h0, h1, l0, l1);
            int o = brow * 40 + bcb + 4 * j;
            *(uint2*)&sBhi[o] = make_uint2(h0, h1);
            *(uint2*)&sBlo[o] = make_uint2(l0, l1);
        }
        __syncthreads();

        // ---- compute: 2 k16 steps ----
        #pragma unroll
        for (int ks = 0; ks < 2; ks++) {
            unsigned ah[2][4], al[2][4], bh[4][2], bl[4][2];
            LDSM_X4(ah[0][0], ah[0][1], ah[0][2], ah[0][3], uAhi + aoff + ks * 32);
            LDSM_X4(ah[1][0], ah[1][1], ah[1][2], ah[1][3], uAhi + aoff + 16 * 80 + ks * 32);
            LDSM_X4(al[0][0], al[0][1], al[0][2], al[0][3], uAlo + aoff + ks * 32);
            LDSM_X4(al[1][0], al[1][1], al[1][2], al[1][3], uAlo + aoff + 16 * 80 + ks * 32);
            LDSM_X4(bh[0][0], bh[0][1], bh[1][0], bh[1][1], uBhi + boff + ks * 32);
            LDSM_X4(bh[2][0], bh[2][1], bh[3][0], bh[3][1], uBhi + boff + 16 * 80 + ks * 32);
            LDSM_X4(bl[0][0], bl[0][1], bl[1][0], bl[1][1], uBlo + boff + ks * 32);
            LDSM_X4(bl[2][0], bl[2][1], bl[3][0], bl[3][1], uBlo + boff + 16 * 80 + ks * 32);
            #pragma unroll
            for (int mt = 0; mt < 2; mt++)
                #pragma unroll
                for (int nt = 0; nt < 4; nt++) {
                    MMA_BF16(c[mt][nt], ah[mt], bh[nt][0], bh[nt][1]);
                    MMA_BF16(c[mt][nt], al[mt], bh[nt][0], bh[nt][1]);
                    MMA_BF16(c[mt][nt], ah[mt], bl[nt][0], bl[nt][1]);
                }
        }
    }

    // ---------------- Epilogue (R3-proven logic): bias, store, stats --------
    const int gq = lane >> 2;   // 0..7 (row group)
    const int gr = lane & 3;    // 0..3 (col pair)

    float sS[4][2], sQ[4][2];
    #pragma unroll
    for (int nt = 0; nt < 4; nt++) { sS[nt][0] = sS[nt][1] = 0.f; sQ[nt][0] = sQ[nt][1] = 0.f; }

    #pragma unroll
    for (int nt = 0; nt < 4; nt++) {
        int col = n0 + nwarp * 32 + nt * 8 + 2 * gr;
        bool cok = col < HIDDEN;
        float bb0 = cok ? bvec[col]     : 0.f;
        float bb1 = cok ? bvec[col + 1] : 0.f;
        #pragma unroll
        for (int mt = 0; mt < 2; mt++) {
            int r0 = m0 + mwarp * 32 + mt * 16 + gq;
            float v00 = c[mt][nt][0] + bb0;
            float v01 = c[mt][nt][1] + bb1;
            float v10 = c[mt][nt][2] + bb0;
            float v11 = c[mt][nt][3] + bb1;
            if (cok) {
                *(float2*)&C[(size_t)r0 * HIDDEN + col]       = make_float2(v00, v01);
                *(float2*)&C[(size_t)(r0 + 8) * HIDDEN + col] = make_float2(v10, v11);
            } else { v00 = v01 = v10 = v11 = 0.f; }
            sS[nt][0] += v00 + v10;
            sS[nt][1] += v01 + v11;
            sQ[nt][0] = fmaf(v00, v00, fmaf(v10, v10, sQ[nt][0]));
            sQ[nt][1] = fmaf(v01, v01, fmaf(v11, v11, sQ[nt][1]));
        }
    }
    #pragma unroll
    for (int nt = 0; nt < 4; nt++)
        #pragma unroll
        for (int p = 0; p < 2; p++) {
            #pragma unroll
            for (int off = 4; off <= 16; off <<= 1) {
                sS[nt][p] += __shfl_xor_sync(0xffffffffu, sS[nt][p], off);
                sQ[nt][p] += __shfl_xor_sync(0xffffffffu, sQ[nt][p], off);
            }
        }
    __syncthreads();  // smem stage buffers no longer needed; reuse barriers
    if (gq == 0) {
        #pragma unroll
        for (int nt = 0; nt < 4; nt++)
            #pragma unroll
            for (int p = 0; p < 2; p++) {
                int cl = nwarp * 32 + nt * 8 + 2 * gr + p;
                redS[mwarp * 64 + cl] = sS[nt][p];
                redQ[mwarp * 64 + cl] = sQ[nt][p];
            }
    }
    __syncthreads();
    if (tid < 64) {
        int col = n0 + tid;
        if (col < HIDDEN) {
            float s = redS[tid] + redS[64 + tid] + redS[128 + tid] + redS[192 + tid];
            float q = redQ[tid] + redQ[64 + tid] + redQ[128 + tid] + redQ[192 + tid];
            g_parts[blockIdx.x * HIDDEN + col] = s;
            g_partq[blockIdx.x * HIDDEN + col] = q;
        }
    }
}

// ---------------------------------------------------------------------------
// Kernel 3: finalize BN stats -> folded scale/shift. grid=400, block=128.
// ---------------------------------------------------------------------------
__global__ __launch_bounds__(128)
void finalize_kernel(const float* __restrict__ g, const float* __restrict__ bt)
{
    const int col = blockIdx.x;
    const int tid = threadIdx.x;
    __shared__ float ss[128];
    __shared__ float sq[128];
    ss[tid] = g_parts[tid * HIDDEN + col];
    sq[tid] = g_partq[tid * HIDDEN + col];
    __syncthreads();
    #pragma unroll
    for (int st = 64; st > 0; st >>= 1) {
        if (tid < st) { ss[tid] += ss[tid + st]; sq[tid] += sq[tid + st]; }
        __syncthreads();
    }
    if (tid == 0) {
        float mu  = ss[0] * (1.0f / N_ROWS);
        float var = sq[0] * (1.0f / N_ROWS) - mu * mu;
        float a = g[col] * rsqrtf(var + BN_EPS);
        g_sa[col] = a;
        g_sc[col] = fmaf(-a, mu, bt[col]);
    }
}

// ---------------------------------------------------------------------------
// Kernel 4: final BN + ReLU fused with row-sum, adds into out[n].
// ---------------------------------------------------------------------------
__global__ __launch_bounds__(256)
void bn_relu_rowsum_kernel(float* __restrict__ out)
{
    const int warp = threadIdx.x >> 5;
    const int lane = threadIdx.x & 31;
    const int n = (blockIdx.x << 3) + warp;
    const float* row = g_HA + (size_t)n * HIDDEN;
    float s = 0.f;
    for (int c = lane; c < HIDDEN; c += 32)
        s += fmaxf(fmaf(g_sa[c], row[c], g_sc[c]), 0.f);
    #pragma unroll
    for (int off = 16; off > 0; off >>= 1)
        s += __shfl_xor_sync(0xffffffffu, s, off);
    if (lane == 0) out[n] += s;
}

// ---------------------------------------------------------------------------
extern "C" void kernel_launch(void* const* d_in, const int* in_sizes, int n_in,
                              void* d_out, int out_size)
{
    const int* Xi        = (const int*)d_in[0];
    const float* Xv      = (const float*)d_in[1];
    const float* emb1    = (const float*)d_in[2];
    const float* emb2    = (const float*)d_in[3];
    const float* W1      = (const float*)d_in[4];
    const float* b1      = (const float*)d_in[5];
    const float* g1      = (const float*)d_in[6];
    const float* bt1     = (const float*)d_in[7];
    const float* W2      = (const float*)d_in[8];
    const float* b2      = (const float*)d_in[9];
    const float* g2      = (const float*)d_in[10];
    const float* bt2     = (const float*)d_in[11];
    const float* W3      = (const float*)d_in[12];
    const float* b3      = (const float*)d_in[13];
    const float* g3      = (const float*)d_in[14];
    const float* bt3     = (const float*)d_in[15];
    const float* bias    = (const float*)d_in[16];
    float* out = (float*)d_out;

    gather_fm_kernel<<<N_ROWS / 16, dim3(16, 16)>>>(Xi, Xv, emb1, emb2, bias, out);

    dim3 ggrid(MBLK, (HIDDEN + 63) / 64);   // (128, 7)

    gemm_bf16s<K1, false, 0, 1><<<ggrid, 256>>>(W1, b1);
    finalize_kernel<<<HIDDEN, 128>>>(g1, bt1);

    gemm_bf16s<HIDDEN, true, 1, 2><<<ggrid, 256>>>(W2, b2);
    finalize_kernel<<<HIDDEN, 128>>>(g2, bt2);

    gemm_bf16s<HIDDEN, true, 2, 1><<<ggrid, 256>>>(W3, b3);
    finalize_kernel<<<HIDDEN, 128>>>(g3, bt3);

    bn_relu_rowsum_kernel<<<N_ROWS / 8, 256>>>(out);
}